// round 14
// baseline (speedup 1.0000x reference)
#include <cuda_runtime.h>
#include <math_constants.h>
#include <cstdint>

// Fixed problem shape: [16, 17, 384, 384] fp32
#define HM_W 384
#define HM_H 384
#define HM_PLANES 272
#define BAND 32
#define BANDS (HM_H / BAND)            // 12
#define TPB 256                        // 8 warps
#define NWARPS (TPB / 32)
#define ROWS_PER_WARP (BAND / NWARPS)  // 4
#define TILE_ROWS (BAND + 2)           // 34 (band + top/bottom halo)
#define TILE_BYTES (TILE_ROWS * HM_W * 4)  // 52224
#define NBLOCKS (HM_PLANES * BANDS)    // 3264

#define SIG_THRESH 0.05f
// logit(0.05): sigmoid(x) > 0.05  <=>  x > LOGIT_THRESH
#define LOGIT_THRESH (-2.9444389791664403f)
#define FULLM 0xffffffffu

__device__ __forceinline__ float max3(float a, float b, float c) {
    return fmaxf(a, fmaxf(b, c));
}

__device__ __forceinline__ float4 max3v(const float4& a, const float4& b, const float4& c) {
    float4 r;
    r.x = max3(a.x, b.x, c.x);
    r.y = max3(a.y, b.y, c.y);
    r.z = max3(a.z, b.z, c.z);
    r.w = max3(a.w, b.w, c.w);
    return r;
}

// peak score: sigmoid(x) if (3x3 max == x) && x > logit(0.05), else 0
__device__ __forceinline__ float peak(float m, float x) {
    float e = __expf(-x);
    float s = __fdividef(1.0f, 1.0f + e);
    return (m == x && x > LOGIT_THRESH) ? s : 0.0f;
}

__device__ __forceinline__ float4 peaks4(const float4& c, const float4& v,
                                         float vl, float vr) {
    float4 r;
    r.x = peak(max3(vl,  v.x, v.y), c.x);
    r.y = peak(max3(v.x, v.y, v.z), c.y);
    r.z = peak(max3(v.y, v.z, v.w), c.z);
    r.w = peak(max3(v.z, v.w, vr),  c.w);
    return r;
}

__device__ __forceinline__ uint32_t smem_u32(const void* p) {
    uint32_t a;
    asm("{ .reg .u64 t; cvta.to.shared.u64 t, %1; cvt.u32.u64 %0, t; }"
        : "=r"(a) : "l"(p));
    return a;
}

__global__ __launch_bounds__(TPB, 4)
void heatmap_peaks_kernel(const float* __restrict__ in, float* __restrict__ out) {
    extern __shared__ __align__(16) float tile[];   // TILE_ROWS * HM_W floats
    __shared__ uint64_t mbar;

    const int tid  = threadIdx.x;
    const int lane = tid & 31;
    const int warp = tid >> 5;

    const int plane = blockIdx.x / BANDS;
    const int band  = blockIdx.x - plane * BANDS;
    const int r0    = band * BAND;

    const float* __restrict__ p = in  + (size_t)plane * (HM_W * HM_H);
    float* __restrict__       o = out + (size_t)plane * (HM_W * HM_H);

    // Contiguous copy range: rows [rs, re] of this plane (band + available halo)
    const int rs = (r0 > 0) ? (r0 - 1) : 0;
    const int re_ = r0 + BAND;                       // bottom halo row
    const int re = (re_ < HM_H) ? re_ : (HM_H - 1);
    const int nrows = re - rs + 1;
    const int slot0 = rs - (r0 - 1);                 // 0 normally, 1 for the top band
    const uint32_t bytes = (uint32_t)nrows * HM_W * sizeof(float);

    const uint32_t mbar_a = smem_u32(&mbar);
    const uint32_t dst_a  = smem_u32(&tile[slot0 * HM_W]);

    if (tid == 0) {
        asm volatile("mbarrier.init.shared.b64 [%0], %1;"
                     :: "r"(mbar_a), "r"(1) : "memory");
    }
    __syncthreads();

    if (tid == 0) {
        asm volatile("mbarrier.arrive.expect_tx.shared.b64 _, [%0], %1;"
                     :: "r"(mbar_a), "r"(bytes) : "memory");
        asm volatile("cp.async.bulk.shared::cluster.global.mbarrier::complete_tx::bytes "
                     "[%0], [%1], %2, [%3];"
                     :: "r"(dst_a), "l"(p + (size_t)rs * HM_W), "r"(bytes), "r"(mbar_a)
                     : "memory");
    }

    // Wait for the bulk copy (phase 0)
    {
        uint32_t done;
        asm volatile(
            "{\n\t"
            ".reg .pred q;\n\t"
            "mbarrier.try_wait.parity.acquire.cta.shared::cta.b64 q, [%1], 0;\n\t"
            "selp.b32 %0, 1, 0, q;\n\t"
            "}"
            : "=r"(done) : "r"(mbar_a) : "memory");
        while (!done) {
            asm volatile(
                "{\n\t"
                ".reg .pred q;\n\t"
                "mbarrier.try_wait.parity.acquire.cta.shared::cta.b64 q, [%1], 0, 0x989680;\n\t"
                "selp.b32 %0, 1, 0, q;\n\t"
                "}"
                : "=r"(done) : "r"(mbar_a) : "memory");
        }
    }

    // ---- compute from SMEM: warp w handles rows [r0+4w, r0+4w+4) ----
    const int wr = r0 + ROWS_PER_WARP * warp;        // first output row of this warp
    const int baseSlot = ROWS_PER_WARP * warp;       // smem slot of row wr-1
    const int xb = lane * 4;                         // interleaved: cols xb, xb+128, xb+256
    const float NEG = -CUDART_INF_F;
    const float4 NEG4 = make_float4(NEG, NEG, NEG, NEG);

    float4 P0, P1, P2, C0, C1, C2;
    if (wr > 0) {
        const float* t = &tile[baseSlot * HM_W + xb];
        P0 = *(const float4*)(t);
        P1 = *(const float4*)(t + 128);
        P2 = *(const float4*)(t + 256);
    } else {
        P0 = NEG4; P1 = NEG4; P2 = NEG4;
    }
    {
        const float* t = &tile[(baseSlot + 1) * HM_W + xb];
        C0 = *(const float4*)(t);
        C1 = *(const float4*)(t + 128);
        C2 = *(const float4*)(t + 256);
    }

    float* op = o + (size_t)wr * HM_W + xb;

    #pragma unroll
    for (int i = 0; i < ROWS_PER_WARP; ++i) {
        const int row = wr + i;

        float4 N0, N1, N2;
        if (row + 1 < HM_H) {
            const float* t = &tile[(baseSlot + 2 + i) * HM_W + xb];
            N0 = *(const float4*)(t);
            N1 = *(const float4*)(t + 128);
            N2 = *(const float4*)(t + 256);
        } else {
            N0 = NEG4; N1 = NEG4; N2 = NEG4;
        }

        // Vertical 3-max per column
        float4 v0 = max3v(P0, C0, N0);
        float4 v1 = max3v(P1, C1, N1);
        float4 v2 = max3v(P2, C2, N2);

        // Horizontal neighbors via warp shuffles
        float l0 = __shfl_up_sync(FULLM, v0.w, 1);
        float l1 = __shfl_up_sync(FULLM, v1.w, 1);
        float l2 = __shfl_up_sync(FULLM, v2.w, 1);
        float b01 = __shfl_sync(FULLM, v0.w, 31);
        float b12 = __shfl_sync(FULLM, v1.w, 31);
        float r0s = __shfl_down_sync(FULLM, v0.x, 1);
        float r1s = __shfl_down_sync(FULLM, v1.x, 1);
        float r2s = __shfl_down_sync(FULLM, v2.x, 1);
        float f10 = __shfl_sync(FULLM, v1.x, 0);
        float f21 = __shfl_sync(FULLM, v2.x, 0);

        if (lane == 0)  { l0 = NEG; l1 = b01; l2 = b12; }
        if (lane == 31) { r0s = f10; r1s = f21; r2s = NEG; }

        // Peak test + sigmoid, store row
        float4 o0 = peaks4(C0, v0, l0, r0s);
        float4 o1 = peaks4(C1, v1, l1, r1s);
        float4 o2 = peaks4(C2, v2, l2, r2s);

        *(float4*)(op)       = o0;
        *(float4*)(op + 128) = o1;
        *(float4*)(op + 256) = o2;
        op += HM_W;

        // Rotate carried rows
        P0 = C0; P1 = C1; P2 = C2;
        C0 = N0; C1 = N1; C2 = N2;
    }
}

extern "C" void kernel_launch(void* const* d_in, const int* in_sizes, int n_in,
                              void* d_out, int out_size) {
    (void)in_sizes; (void)n_in; (void)out_size;
    const float* heatmaps = (const float*)d_in[0];
    float* out = (float*)d_out;

    cudaFuncSetAttribute(heatmap_peaks_kernel,
                         cudaFuncAttributeMaxDynamicSharedMemorySize, TILE_BYTES);
    heatmap_peaks_kernel<<<NBLOCKS, TPB, TILE_BYTES>>>(heatmaps, out);
}